// round 7
// baseline (speedup 1.0000x reference)
#include <cuda_runtime.h>
#include <cstdint>
#include <math.h>

#define DIM 128
#define TILE 128
#define BMAX 8192
#define NTMAX 64
#define TPB 4                  // B-tiles per CTA; A tile stays resident
#define LDW 68                 // smem row stride in words (272B): banks (4g+t)%32 distinct

__device__ float g_nsk[BMAX];
__device__ float g_nim[BMAX];
__device__ uint32_t g_skbf[BMAX * 64];                    // bf16x2-packed rows
__device__ uint32_t g_imbf[BMAX * 64];
__device__ float g_partial[(size_t)BMAX * NTMAX * 4];     // per (row, bn, wn-quarter)
__device__ float g_diag[BMAX];                            // exact fp32 diagonal distance
__device__ float g_rowval[BMAX];

static __device__ __forceinline__ uint32_t s2u(const void* p) {
    uint32_t a;
    asm("{ .reg .u64 t; cvta.to.shared.u64 t, %1; cvt.u32.u64 %0, t; }" : "=r"(a) : "l"(p));
    return a;
}
static __device__ __forceinline__ void cpa16(uint32_t dst, const void* src) {
    asm volatile("cp.async.cg.shared.global [%0], [%1], 16;" :: "r"(dst), "l"(src) : "memory");
}
#define CP_COMMIT() asm volatile("cp.async.commit_group;" ::: "memory")
#define CP_WAIT0()  asm volatile("cp.async.wait_group 0;" ::: "memory")
#define CP_WAIT1()  asm volatile("cp.async.wait_group 1;" ::: "memory")

static __device__ __forceinline__ uint32_t packbf(float lo, float hi) {
    uint32_t r;
    asm("cvt.rn.bf16x2.f32 %0, %1, %2;" : "=r"(r) : "f"(hi), "f"(lo));
    return r;
}
static __device__ __forceinline__ void mma16(float* c, const uint32_t* a, const uint32_t* b) {
    asm("mma.sync.aligned.m16n8k16.row.col.f32.bf16.bf16.f32 "
        "{%0,%1,%2,%3}, {%4,%5,%6,%7}, {%8,%9}, {%0,%1,%2,%3};"
        : "+f"(c[0]), "+f"(c[1]), "+f"(c[2]), "+f"(c[3])
        : "r"(a[0]), "r"(a[1]), "r"(a[2]), "r"(a[3]), "r"(b[0]), "r"(b[1]));
}

// ---------------------------------------------------------------------------
// One warp per row: y=0/1 -> fp32 norms + bf16 pack; y=2 -> exact fp32 diag.
// ---------------------------------------------------------------------------
__global__ void prep_kernel(const float* __restrict__ sk,
                            const float* __restrict__ im, int B) {
    int row = (blockIdx.x * blockDim.x + threadIdx.x) >> 5;
    int lane = threadIdx.x & 31;
    if (row >= B) return;
    if (blockIdx.y < 2) {
        const float* src = blockIdx.y ? im : sk;
        float* ndst = blockIdx.y ? g_nim : g_nsk;
        uint32_t* bdst = blockIdx.y ? g_imbf : g_skbf;
        float4 v = ((const float4*)(src + (size_t)row * DIM))[lane];
        bdst[row * 64 + lane * 2]     = packbf(v.x, v.y);
        bdst[row * 64 + lane * 2 + 1] = packbf(v.z, v.w);
        float s = v.x * v.x + v.y * v.y + v.z * v.z + v.w * v.w;
#pragma unroll
        for (int o = 16; o; o >>= 1) s += __shfl_xor_sync(0xffffffffu, s, o);
        if (lane == 0) ndst[row] = s;
    } else {
        float4 a = ((const float4*)(sk + (size_t)row * DIM))[lane];
        float4 b = ((const float4*)(im + (size_t)row * DIM))[lane];
        float dx = a.x - b.x, dy = a.y - b.y, dz = a.z - b.z, dw = a.w - b.w;
        float s = dx * dx + dy * dy + dz * dz + dw * dw;
#pragma unroll
        for (int o = 16; o; o >>= 1) s += __shfl_xor_sync(0xffffffffu, s, o);
        if (lane == 0) g_diag[row] = sqrtf(s);
    }
}

// ---------------------------------------------------------------------------
// Software-pipelined bf16 MMA + fused distance/exp epilogue.
// 512 threads = 16 warps (4 m-blocks x 4 n-blocks), warp tile 32x32.
// 4 warps/SMSP for latency hiding. Epilogue of tile t-1 interleaved
// chunk-wise ((mt,nb) pair per k-step) into mainloop of tile t.
// ---------------------------------------------------------------------------
__global__ void __launch_bounds__(512, 1)
dist_mma(int nt) {
    extern __shared__ uint32_t smw[];
    const uint32_t sbase = s2u(smw);
    uint32_t* As = smw;
    const uint32_t NORM_OFF = 3u * 128u * LDW;            // word offset of norm buffer
    float* nsm = (float*)(smw + NORM_OFF);                // 4*128 floats

    const int tid = threadIdx.x;
    const int wid = tid >> 5;
    const int lane = tid & 31;
    const int g = lane >> 2;
    const int t = lane & 3;
    const int wm = wid & 3;        // m-block: 32 rows
    const int wn = wid >> 2;       // n-block: 32 cols

    const int ntg = nt / TPB;
    const int bm = blockIdx.x / ntg;
    const int bn0 = (blockIdx.x % ntg) * TPB;

    // ---- prologue: A, B0, norms (group 0); B1 prefetch (group 1) ----
    {
        const uint32_t* Ag = g_skbf + (size_t)bm * TILE * 64;
        const uint32_t* Bg = g_imbf + (size_t)bn0 * TILE * 64;
#pragma unroll
        for (int it = 0; it < 4; it++) {
            int c = it * 512 + tid;          // 0..2047 16B-chunks
            int row = c >> 4, ch = c & 15;
            uint32_t doff = (uint32_t)row * 272 + (uint32_t)ch * 16;
            cpa16(sbase + doff, Ag + row * 64 + ch * 4);
            cpa16(sbase + 128 * LDW * 4 + doff, Bg + row * 64 + ch * 4);
        }
        if (tid < 128)
            cpa16(sbase + NORM_OFF * 4 + (uint32_t)tid * 16, g_nim + (size_t)bn0 * TILE + tid * 4);
        CP_COMMIT();
        const uint32_t* Bg1 = g_imbf + (size_t)(bn0 + 1) * TILE * 64;
#pragma unroll
        for (int it = 0; it < 4; it++) {
            int c = it * 512 + tid;
            int row = c >> 4, ch = c & 15;
            cpa16(sbase + 2 * 128 * LDW * 4 + (uint32_t)row * 272 + (uint32_t)ch * 16,
                  Bg1 + row * 64 + ch * 4);
        }
        CP_COMMIT();
        CP_WAIT1();
    }
    __syncthreads();

    float nr[2][2];
#pragma unroll
    for (int mt = 0; mt < 2; mt++)
#pragma unroll
        for (int h = 0; h < 2; h++)
            nr[mt][h] = g_nsk[bm * TILE + wm * 32 + mt * 16 + h * 8 + g];

    const int a_base = (wm * 32 + g) * LDW + t;
    const int b_base = (wn * 32 + g) * LDW + t;

    float acc[2][2][4][4];     // [buf][mt][nb][r]
    float rs[2][2];

#pragma unroll
    for (int tt = 0; tt <= TPB; tt++) {
        const bool do_main = (tt < TPB);
        const bool do_epi = (tt > 0);
        const int nbuf = tt & 1;
        const int bn_old = bn0 + tt - 1;

        // prefetch B[tt+1] into buffer (tt+1)&1
        if (tt + 1 < TPB) {
            const uint32_t* Bg = g_imbf + (size_t)(bn0 + tt + 1) * TILE * 64;
            uint32_t dbuf = sbase + (1 + ((tt + 1) & 1)) * 128 * LDW * 4;
#pragma unroll
            for (int it = 0; it < 4; it++) {
                int c = it * 512 + tid;
                int row = c >> 4, ch = c & 15;
                cpa16(dbuf + (uint32_t)row * 272 + (uint32_t)ch * 16, Bg + row * 64 + ch * 4);
            }
            CP_COMMIT();
        }

        float (*accN)[4][4] = acc[nbuf];
        float (*accO)[4][4] = acc[nbuf ^ 1];
        const uint32_t* Bs = smw + (1 + (tt & 1)) * 128 * LDW;

        if (do_main) {
#pragma unroll
            for (int mt = 0; mt < 2; mt++)
#pragma unroll
                for (int nb = 0; nb < 4; nb++)
#pragma unroll
                    for (int r = 0; r < 4; r++) accN[mt][nb][r] = 0.f;
        }
        if (do_epi) { rs[0][0] = rs[0][1] = rs[1][0] = rs[1][1] = 0.f; }

        // 8 k-steps of 16; 1 (mt,nb) epilogue chunk of previous tile per k-step
#pragma unroll
        for (int ks = 0; ks < 8; ks++) {
            if (do_main) {
                const int ko = ks * 8;       // word offset: 16 bf16 = 8 words
                uint32_t a[2][4], b[4][2];
#pragma unroll
                for (int mt = 0; mt < 2; mt++) {
                    int ba = a_base + mt * 16 * LDW + ko;
                    a[mt][0] = As[ba];
                    a[mt][1] = As[ba + 8 * LDW];
                    a[mt][2] = As[ba + 4];
                    a[mt][3] = As[ba + 8 * LDW + 4];
                }
#pragma unroll
                for (int nb = 0; nb < 4; nb++) {
                    int bb = b_base + nb * 8 * LDW + ko;
                    b[nb][0] = Bs[bb];
                    b[nb][1] = Bs[bb + 4];
                }
#pragma unroll
                for (int mt = 0; mt < 2; mt++)
#pragma unroll
                    for (int nb = 0; nb < 4; nb++) mma16(accN[mt][nb], a[mt], b[nb]);
            }
            if (do_epi) {
                const int emt = ks >> 2;            // 0..1
                const int enb = ks & 3;             // 0..3
                float2 nc = *(const float2*)&nsm[(tt - 1) * 128 + wn * 32 + enb * 8 + t * 2];
#pragma unroll
                for (int h = 0; h < 2; h++) {
                    float base = nr[emt][h];
                    float sq0 = fmaxf(fmaf(-2.f, accO[emt][enb][h * 2 + 0], base + nc.x), 0.f);
                    float sq1 = fmaxf(fmaf(-2.f, accO[emt][enb][h * 2 + 1], base + nc.y), 0.f);
                    float d0, d1, e0, e1;
                    asm("sqrt.approx.f32 %0, %1;" : "=f"(d0) : "f"(sq0));
                    asm("sqrt.approx.f32 %0, %1;" : "=f"(d1) : "f"(sq1));
                    asm("ex2.approx.f32 %0, %1;" : "=f"(e0) : "f"(d0 * -1.4426950408889634f));
                    asm("ex2.approx.f32 %0, %1;" : "=f"(e1) : "f"(d1 * -1.4426950408889634f));
                    rs[emt][h] += e0 + e1;
                }
            }
        }

        if (do_epi) {
#pragma unroll
            for (int mt = 0; mt < 2; mt++) {
#pragma unroll
                for (int h = 0; h < 2; h++) {
                    float v = rs[mt][h];
                    v += __shfl_xor_sync(0xffffffffu, v, 1);
                    v += __shfl_xor_sync(0xffffffffu, v, 2);
                    if (t == 0) {
                        int r_local = wm * 32 + mt * 16 + h * 8 + g;
                        g_partial[((size_t)(bm * TILE + r_local) * nt + bn_old) * 4 + wn] = v;
                    }
                }
            }
        }

        if (do_main) {
            CP_WAIT0();
            __syncthreads();
        }
    }
}

// ---------------------------------------------------------------------------
// Per-row: log(sum of 4*nt partials) + exact diag (fixed order, deterministic)
// ---------------------------------------------------------------------------
__global__ void rows_kernel(int B, int nt) {
    int i = blockIdx.x * blockDim.x + threadIdx.x;
    if (i >= B) return;
    float s = 0.f;
    const float* p = g_partial + (size_t)i * nt * 4;
    for (int t = 0; t < 4 * nt; t++) s += p[t];
    g_rowval[i] = logf(s) + g_diag[i];
}

__global__ void final_kernel(float* __restrict__ out, int B, int out_size) {
    __shared__ float sm[1024];
    int tid = threadIdx.x;
    float s = 0.f;
    for (int i = tid; i < B; i += 1024) s += g_rowval[i];
    sm[tid] = s;
    __syncthreads();
    for (int o = 512; o; o >>= 1) {
        if (tid < o) sm[tid] += sm[tid + o];
        __syncthreads();
    }
    if (tid == 0) {
        float loss = sm[0] / (float)B;
        for (int i = 0; i < out_size; i++) out[i] = loss;
    }
}

extern "C" void kernel_launch(void* const* d_in, const int* in_sizes, int n_in,
                              void* d_out, int out_size) {
    const float* sk = (const float*)d_in[0];
    const float* im = (const float*)d_in[1];
    float* out = (float*)d_out;

    int B = in_sizes[0] / DIM;   // 8192
    int nt = B / TILE;           // 64

    prep_kernel<<<dim3(B / 8, 3), 256>>>(sk, im, B);

    static const int SMEM_BYTES = (3 * 128 * LDW + 4 * 128) * 4;   // 106496
    cudaFuncSetAttribute(dist_mma, cudaFuncAttributeMaxDynamicSharedMemorySize, SMEM_BYTES);
    int ncta = nt * (nt / TPB);  // 1024
    dist_mma<<<ncta, 512, SMEM_BYTES>>>(nt);

    rows_kernel<<<(B + 255) / 256, 256>>>(B, nt);
    final_kernel<<<1, 1024>>>(out, B, out_size);
}

// round 8
// speedup vs baseline: 1.2202x; 1.2202x over previous
#include <cuda_runtime.h>
#include <cstdint>
#include <math.h>

#define DIM 128
#define TILE 128
#define BMAX 8192
#define NTMAX 64
#define TPB 4                  // B-tiles per CTA; A tile stays resident
#define LDW 68                 // smem row stride in words (272B): banks (4g+t)%32 distinct

__device__ float g_nsk[BMAX];
__device__ float g_nim[BMAX];
__device__ uint32_t g_skbf[BMAX * 64];                    // bf16x2-packed rows
__device__ uint32_t g_imbf[BMAX * 64];
__device__ float g_partial[(size_t)BMAX * NTMAX * 2];     // per (row, bn, wn-half)
__device__ float g_diag[BMAX];                            // exact fp32 diagonal distance
__device__ float g_rowval[BMAX];

static __device__ __forceinline__ uint32_t s2u(const void* p) {
    uint32_t a;
    asm("{ .reg .u64 t; cvta.to.shared.u64 t, %1; cvt.u32.u64 %0, t; }" : "=r"(a) : "l"(p));
    return a;
}
static __device__ __forceinline__ void cpa16(uint32_t dst, const void* src) {
    asm volatile("cp.async.cg.shared.global [%0], [%1], 16;" :: "r"(dst), "l"(src) : "memory");
}
#define CP_COMMIT() asm volatile("cp.async.commit_group;" ::: "memory")
#define CP_WAIT0()  asm volatile("cp.async.wait_group 0;" ::: "memory")
#define CP_WAIT1()  asm volatile("cp.async.wait_group 1;" ::: "memory")

static __device__ __forceinline__ uint32_t packbf(float lo, float hi) {
    uint32_t r;
    asm("cvt.rn.bf16x2.f32 %0, %1, %2;" : "=r"(r) : "f"(hi), "f"(lo));
    return r;
}
static __device__ __forceinline__ void mma16(float* c, const uint32_t* a, const uint32_t* b) {
    asm("mma.sync.aligned.m16n8k16.row.col.f32.bf16.bf16.f32 "
        "{%0,%1,%2,%3}, {%4,%5,%6,%7}, {%8,%9}, {%0,%1,%2,%3};"
        : "+f"(c[0]), "+f"(c[1]), "+f"(c[2]), "+f"(c[3])
        : "r"(a[0]), "r"(a[1]), "r"(a[2]), "r"(a[3]), "r"(b[0]), "r"(b[1]));
}

// ---------------------------------------------------------------------------
// One warp per row: y=0/1 -> fp32 norms + bf16 pack; y=2 -> exact fp32 diag.
// ---------------------------------------------------------------------------
__global__ void prep_kernel(const float* __restrict__ sk,
                            const float* __restrict__ im, int B) {
    int row = (blockIdx.x * blockDim.x + threadIdx.x) >> 5;
    int lane = threadIdx.x & 31;
    if (row >= B) return;
    if (blockIdx.y < 2) {
        const float* src = blockIdx.y ? im : sk;
        float* ndst = blockIdx.y ? g_nim : g_nsk;
        uint32_t* bdst = blockIdx.y ? g_imbf : g_skbf;
        float4 v = ((const float4*)(src + (size_t)row * DIM))[lane];
        bdst[row * 64 + lane * 2]     = packbf(v.x, v.y);
        bdst[row * 64 + lane * 2 + 1] = packbf(v.z, v.w);
        float s = v.x * v.x + v.y * v.y + v.z * v.z + v.w * v.w;
#pragma unroll
        for (int o = 16; o; o >>= 1) s += __shfl_xor_sync(0xffffffffu, s, o);
        if (lane == 0) ndst[row] = s;
    } else {
        float4 a = ((const float4*)(sk + (size_t)row * DIM))[lane];
        float4 b = ((const float4*)(im + (size_t)row * DIM))[lane];
        float dx = a.x - b.x, dy = a.y - b.y, dz = a.z - b.z, dw = a.w - b.w;
        float s = dx * dx + dy * dy + dz * dz + dw * dw;
#pragma unroll
        for (int o = 16; o; o >>= 1) s += __shfl_xor_sync(0xffffffffu, s, o);
        if (lane == 0) g_diag[row] = sqrtf(s);
    }
}

// ---------------------------------------------------------------------------
// Software-pipelined bf16 MMA + fused distance/exp epilogue (occ 1).
// 8 warps, warp tile 32x64. Three-level pipeline per k-step:
//   LDS frags(k+1)  ->  epilogue MUFU chunk (covers LDS latency)  ->  MMA(k)
// so HMMA issue never waits on shared memory.
// ---------------------------------------------------------------------------
__global__ void __launch_bounds__(256, 1)
dist_mma(int nt) {
    extern __shared__ uint32_t smw[];
    const uint32_t sbase = s2u(smw);
    uint32_t* As = smw;
    const uint32_t NORM_OFF = 3u * 128u * LDW;            // word offset of norm buffer
    float* nsm = (float*)(smw + NORM_OFF);                // 4*128 floats

    const int tid = threadIdx.x;
    const int lane = tid & 31;
    const int wid = tid >> 5;
    const int g = lane >> 2;
    const int t = lane & 3;
    const int wm = wid & 3;        // m-block: 32 rows
    const int wn = wid >> 2;       // n-block: 64 cols

    const int ntg = nt / TPB;
    const int bm = blockIdx.x / ntg;
    const int bn0 = (blockIdx.x % ntg) * TPB;

    // ---- prologue: A, B0, norms (group 0); B1 prefetch (group 1) ----
    {
        const uint32_t* Ag = g_skbf + (size_t)bm * TILE * 64;
        const uint32_t* Bg = g_imbf + (size_t)bn0 * TILE * 64;
#pragma unroll
        for (int it = 0; it < 8; it++) {
            int c = it * 256 + tid;          // 0..2047 16B-chunks
            int row = c >> 4, ch = c & 15;
            uint32_t doff = (uint32_t)row * 272 + (uint32_t)ch * 16;
            cpa16(sbase + doff, Ag + row * 64 + ch * 4);
            cpa16(sbase + 128 * LDW * 4 + doff, Bg + row * 64 + ch * 4);
        }
        if (tid < 128)
            cpa16(sbase + NORM_OFF * 4 + (uint32_t)tid * 16, g_nim + (size_t)bn0 * TILE + tid * 4);
        CP_COMMIT();
        const uint32_t* Bg1 = g_imbf + (size_t)(bn0 + 1) * TILE * 64;
#pragma unroll
        for (int it = 0; it < 8; it++) {
            int c = it * 256 + tid;
            int row = c >> 4, ch = c & 15;
            cpa16(sbase + 2 * 128 * LDW * 4 + (uint32_t)row * 272 + (uint32_t)ch * 16,
                  Bg1 + row * 64 + ch * 4);
        }
        CP_COMMIT();
        CP_WAIT1();
    }
    __syncthreads();

    float nr[2][2];
#pragma unroll
    for (int mt = 0; mt < 2; mt++)
#pragma unroll
        for (int h = 0; h < 2; h++)
            nr[mt][h] = g_nsk[bm * TILE + wm * 32 + mt * 16 + h * 8 + g];

    const int a_base = (wm * 32 + g) * LDW + t;
    const int b_base = (wn * 64 + g) * LDW + t;

    float acc[2][2][8][4];         // [buf][mt][nb][r]
    uint32_t fa[2][2][4];          // [fbuf][mt][r]  fragment double-buffer
    uint32_t fb[2][8][2];          // [fbuf][nb][r]
    float rs[2][2];

#pragma unroll
    for (int tt = 0; tt <= TPB; tt++) {
        const bool do_main = (tt < TPB);
        const bool do_epi = (tt > 0);
        const int nbuf = tt & 1;
        const int bn_old = bn0 + tt - 1;

        // prefetch B[tt+1] into buffer (tt+1)&1
        if (tt + 1 < TPB) {
            const uint32_t* Bg = g_imbf + (size_t)(bn0 + tt + 1) * TILE * 64;
            uint32_t dbuf = sbase + (1 + ((tt + 1) & 1)) * 128 * LDW * 4;
#pragma unroll
            for (int it = 0; it < 8; it++) {
                int c = it * 256 + tid;
                int row = c >> 4, ch = c & 15;
                cpa16(dbuf + (uint32_t)row * 272 + (uint32_t)ch * 16, Bg + row * 64 + ch * 4);
            }
            CP_COMMIT();
        }

        float (*accN)[8][4] = acc[nbuf];
        float (*accO)[8][4] = acc[nbuf ^ 1];
        const uint32_t* Bs = smw + (1 + (tt & 1)) * 128 * LDW;

        if (do_main) {
#pragma unroll
            for (int mt = 0; mt < 2; mt++)
#pragma unroll
                for (int nb = 0; nb < 8; nb++)
#pragma unroll
                    for (int r = 0; r < 4; r++) accN[mt][nb][r] = 0.f;
            // preload fragments for k-step 0
#pragma unroll
            for (int mt = 0; mt < 2; mt++) {
                int ba = a_base + mt * 16 * LDW;
                fa[0][mt][0] = As[ba];
                fa[0][mt][1] = As[ba + 8 * LDW];
                fa[0][mt][2] = As[ba + 4];
                fa[0][mt][3] = As[ba + 8 * LDW + 4];
            }
#pragma unroll
            for (int nb = 0; nb < 8; nb++) {
                int bb = b_base + nb * 8 * LDW;
                fb[0][nb][0] = Bs[bb];
                fb[0][nb][1] = Bs[bb + 4];
            }
        }
        if (do_epi) { rs[0][0] = rs[0][1] = rs[1][0] = rs[1][1] = 0.f; }

        // 8 k-steps: LDS(k+1) -> epi chunk -> MMA(k)
#pragma unroll
        for (int ks = 0; ks < 8; ks++) {
            const int cur = ks & 1;
            const int nxt = cur ^ 1;
            if (do_main && ks < 7) {
                const int ko = (ks + 1) * 8;
#pragma unroll
                for (int mt = 0; mt < 2; mt++) {
                    int ba = a_base + mt * 16 * LDW + ko;
                    fa[nxt][mt][0] = As[ba];
                    fa[nxt][mt][1] = As[ba + 8 * LDW];
                    fa[nxt][mt][2] = As[ba + 4];
                    fa[nxt][mt][3] = As[ba + 8 * LDW + 4];
                }
#pragma unroll
                for (int nb = 0; nb < 8; nb++) {
                    int bb = b_base + nb * 8 * LDW + ko;
                    fb[nxt][nb][0] = Bs[bb];
                    fb[nxt][nb][1] = Bs[bb + 4];
                }
            }
            if (do_epi) {
                // epilogue chunk nb=ks of the previous tile (covers LDS latency)
                float2 nc = *(const float2*)&nsm[(tt - 1) * 128 + wn * 64 + ks * 8 + t * 2];
#pragma unroll
                for (int mt = 0; mt < 2; mt++) {
#pragma unroll
                    for (int h = 0; h < 2; h++) {
                        float base = nr[mt][h];
                        float sq0 = fmaxf(fmaf(-2.f, accO[mt][ks][h * 2 + 0], base + nc.x), 0.f);
                        float sq1 = fmaxf(fmaf(-2.f, accO[mt][ks][h * 2 + 1], base + nc.y), 0.f);
                        float d0, d1, e0, e1;
                        asm("sqrt.approx.f32 %0, %1;" : "=f"(d0) : "f"(sq0));
                        asm("sqrt.approx.f32 %0, %1;" : "=f"(d1) : "f"(sq1));
                        asm("ex2.approx.f32 %0, %1;" : "=f"(e0) : "f"(d0 * -1.4426950408889634f));
                        asm("ex2.approx.f32 %0, %1;" : "=f"(e1) : "f"(d1 * -1.4426950408889634f));
                        rs[mt][h] += e0 + e1;
                    }
                }
            }
            if (do_main) {
#pragma unroll
                for (int mt = 0; mt < 2; mt++)
#pragma unroll
                    for (int nb = 0; nb < 8; nb++) mma16(accN[mt][nb], fa[cur][mt], fb[cur][nb]);
            }
        }

        if (do_epi) {
#pragma unroll
            for (int mt = 0; mt < 2; mt++) {
#pragma unroll
                for (int h = 0; h < 2; h++) {
                    float v = rs[mt][h];
                    v += __shfl_xor_sync(0xffffffffu, v, 1);
                    v += __shfl_xor_sync(0xffffffffu, v, 2);
                    if (t == 0) {
                        int r_local = wm * 32 + mt * 16 + h * 8 + g;
                        g_partial[((size_t)(bm * TILE + r_local) * nt + bn_old) * 2 + wn] = v;
                    }
                }
            }
        }

        if (do_main) {
            CP_WAIT0();
            __syncthreads();
        }
    }
}

// ---------------------------------------------------------------------------
// Per-row: log(sum of 2*nt partials) + exact diag (fixed order, deterministic)
// ---------------------------------------------------------------------------
__global__ void rows_kernel(int B, int nt) {
    int i = blockIdx.x * blockDim.x + threadIdx.x;
    if (i >= B) return;
    float s = 0.f;
    const float* p = g_partial + (size_t)i * nt * 2;
    for (int t = 0; t < 2 * nt; t++) s += p[t];
    g_rowval[i] = logf(s) + g_diag[i];
}

__global__ void final_kernel(float* __restrict__ out, int B, int out_size) {
    __shared__ float sm[1024];
    int tid = threadIdx.x;
    float s = 0.f;
    for (int i = tid; i < B; i += 1024) s += g_rowval[i];
    sm[tid] = s;
    __syncthreads();
    for (int o = 512; o; o >>= 1) {
        if (tid < o) sm[tid] += sm[tid + o];
        __syncthreads();
    }
    if (tid == 0) {
        float loss = sm[0] / (float)B;
        for (int i = 0; i < out_size; i++) out[i] = loss;
    }
}

extern "C" void kernel_launch(void* const* d_in, const int* in_sizes, int n_in,
                              void* d_out, int out_size) {
    const float* sk = (const float*)d_in[0];
    const float* im = (const float*)d_in[1];
    float* out = (float*)d_out;

    int B = in_sizes[0] / DIM;   // 8192
    int nt = B / TILE;           // 64

    prep_kernel<<<dim3(B / 8, 3), 256>>>(sk, im, B);

    static const int SMEM_BYTES = (3 * 128 * LDW + 4 * 128) * 4;   // 106496
    cudaFuncSetAttribute(dist_mma, cudaFuncAttributeMaxDynamicSharedMemorySize, SMEM_BYTES);
    int ncta = nt * (nt / TPB);  // 1024
    dist_mma<<<ncta, 256, SMEM_BYTES>>>(nt);

    rows_kernel<<<(B + 255) / 256, 256>>>(B, nt);
    final_kernel<<<1, 1024>>>(out, B, out_size);
}